// round 8
// baseline (speedup 1.0000x reference)
#include <cuda_runtime.h>

// cosine_regularizer: out = (sum(W) - N)/N^2, W = p p^T, p = row-normalized points.
// Identity: sum(W) = || sum_i p_i ||^2  -> one streaming pass + scalar finalize.
// R8: hierarchical arrival counters. R7 analysis: 512 same-address counter atomics
//     serialize ~30cyc each in the LTS ALU => ~7us drain on the critical path.
//     Now: 16 padded per-replica counters (32 arrivals each, parallel) + 1 global
//     counter (16 arrivals). Epilogue serialization ~7us -> ~0.8us.

constexpr int N_ROWS = 16384;
constexpr int D      = 256;
constexpr int TPB    = 256;                 // 8 warps
constexpr int WARPS  = TPB / 32;
constexpr int NBLK   = 512;                 // 512*8 warps * 4 rows = 16384 rows
constexpr int ROWS_PER_WARP = 4;
constexpr int NREP   = 16;                  // column-sum replicas (R6 win)
constexpr int BLK_PER_REP = NBLK / NREP;    // 32

__device__ float        g_rep[NREP][D];      // zeroed at load; reset by finalize block
__device__ unsigned int g_cnt_rep[NREP][32]; // [r][0] used; 128B padding per counter
__device__ unsigned int g_cnt;               // global counter (16 arrivals)

__global__ void __launch_bounds__(TPB, 3)
k_fused(const float* __restrict__ pts, float* __restrict__ out) {
    const int warp = threadIdx.x >> 5;
    const int lane = threadIdx.x & 31;
    const int t    = threadIdx.x;
    const int gw   = blockIdx.x * WARPS + warp;
    const int rep  = blockIdx.x & (NREP - 1);

    // Batch-issue all 8 LDG.128 for this warp's 4 rows.
    float4 v0[ROWS_PER_WARP], v1[ROWS_PER_WARP];
#pragma unroll
    for (int k = 0; k < ROWS_PER_WARP; k++) {
        const int row = gw + k * (NBLK * WARPS);
        const float4* p = reinterpret_cast<const float4*>(pts) + (size_t)row * (D / 4);
        v0[k] = p[lane];        // cols 4*lane   .. +3
        v1[k] = p[32 + lane];   // cols 128+4*lane .. +3
    }

    // Per-row sum of squares; 4 interleaved warp reductions.
    float ss[ROWS_PER_WARP];
#pragma unroll
    for (int k = 0; k < ROWS_PER_WARP; k++) {
        ss[k] = v0[k].x * v0[k].x + v0[k].y * v0[k].y + v0[k].z * v0[k].z + v0[k].w * v0[k].w
              + v1[k].x * v1[k].x + v1[k].y * v1[k].y + v1[k].z * v1[k].z + v1[k].w * v1[k].w;
    }
#pragma unroll
    for (int off = 16; off > 0; off >>= 1) {
#pragma unroll
        for (int k = 0; k < ROWS_PER_WARP; k++)
            ss[k] += __shfl_xor_sync(0xffffffffu, ss[k], off);
    }

    // rnorm * row into per-lane column accumulators.
    float4 a0 = make_float4(0.f, 0.f, 0.f, 0.f);
    float4 a1 = make_float4(0.f, 0.f, 0.f, 0.f);
#pragma unroll
    for (int k = 0; k < ROWS_PER_WARP; k++) {
        const float rn = rsqrtf(ss[k]);
        a0.x += rn * v0[k].x;  a0.y += rn * v0[k].y;
        a0.z += rn * v0[k].z;  a0.w += rn * v0[k].w;
        a1.x += rn * v1[k].x;  a1.y += rn * v1[k].y;
        a1.z += rn * v1[k].z;  a1.w += rn * v1[k].w;
    }

    // Block-reduce 8 warps' column partials via shared.
    __shared__ float sh[WARPS][D];
    float4* shv = reinterpret_cast<float4*>(sh[warp]);
    shv[lane]      = a0;
    shv[32 + lane] = a1;
    __syncthreads();

    float s = sh[0][t];
#pragma unroll
    for (int w = 1; w < WARPS; w++) s += sh[w][t];

    // Per-column add into this block's replica (32 adds/address chip-wide).
    atomicAdd(&g_rep[rep][t], s);

    // ---- hierarchical last-block detection ----
    __shared__ unsigned int s_isLast;
    __syncthreads();   // block's REDs happen-before t0's release-arrive
    if (t == 0) {
        unsigned int fin = 0u;
        unsigned int old;
        // Level 1: arrive at this replica's counter (32 arrivals, parallel across 16 lines).
        asm volatile("atom.acq_rel.gpu.global.add.u32 %0, [%1], 1;"
                     : "=r"(old) : "l"(&g_cnt_rep[rep][0]) : "memory");
        if (old == (unsigned int)(BLK_PER_REP - 1)) {
            // Level 2: replica-last arrives at the global counter (16 arrivals).
            unsigned int old2;
            asm volatile("atom.acq_rel.gpu.global.add.u32 %0, [%1], 1;"
                         : "=r"(old2) : "l"(&g_cnt) : "memory");
            fin = (old2 == (unsigned int)(NREP - 1)) ? 1u : 0u;
        }
        s_isLast = fin;
    }
    __syncthreads();
    if (!s_isLast) return;

    // Finalize block: acq_rel chain makes all blocks' REDs L2-visible. Fold replicas.
    float v = 0.0f;
#pragma unroll
    for (int r = 0; r < NREP; r++) {
        v += __ldcg(&g_rep[r][t]);
        g_rep[r][t] = 0.0f;                 // reset for next graph replay
    }
    if (t < NREP) g_cnt_rep[t][0] = 0u;     // reset counters
    if (t == 0)   g_cnt = 0u;

    double d = (double)v * (double)v;
#pragma unroll
    for (int off = 16; off > 0; off >>= 1)
        d += __shfl_xor_sync(0xffffffffu, d, off);

    __shared__ double wsum[WARPS];
    if (lane == 0) wsum[warp] = d;
    __syncthreads();
    if (warp == 0) {
        double x = (lane < WARPS) ? wsum[lane] : 0.0;
#pragma unroll
        for (int off = 4; off > 0; off >>= 1)
            x += __shfl_xor_sync(0xffffffffu, x, off);
        if (lane == 0) {
            const double n = (double)N_ROWS;
            out[0] = (float)((x - n) / (n * n));
        }
    }
}

extern "C" void kernel_launch(void* const* d_in, const int* in_sizes, int n_in,
                              void* d_out, int out_size) {
    const float* pts = (const float*)d_in[0];
    (void)in_sizes; (void)n_in; (void)out_size;
    k_fused<<<NBLK, TPB>>>(pts, (float*)d_out);
}

// round 9
// speedup vs baseline: 1.2610x; 1.2610x over previous
#include <cuda_runtime.h>

// cosine_regularizer: out = (sum(W) - N)/N^2, W = p p^T, p = row-normalized points.
// Identity: sum(W) = || sum_i p_i ||^2.
// R9: two-kernel split. k_stream = streaming + fire-and-forget replica REDs (no
//     fence/counter/finalize — kernel boundary provides ordering). k_fin = 1-block
//     fold of the 16 replicas. Also yields per-phase timing from ncu.

constexpr int N_ROWS = 16384;
constexpr int D      = 256;
constexpr int TPB    = 256;                 // 8 warps
constexpr int WARPS  = TPB / 32;
constexpr int NBLK   = 512;                 // 512*8 warps * 4 rows = 16384 rows
constexpr int ROWS_PER_WARP = 4;
constexpr int NREP   = 16;                  // column-sum replicas (R6 win)

__device__ float g_rep[NREP][D];   // zero at load; reset by k_fin each run

__global__ void __launch_bounds__(TPB, 3)
k_stream(const float* __restrict__ pts) {
    const int warp = threadIdx.x >> 5;
    const int lane = threadIdx.x & 31;
    const int t    = threadIdx.x;
    const int gw   = blockIdx.x * WARPS + warp;

    // Batch-issue all 8 LDG.128 for this warp's 4 rows.
    float4 v0[ROWS_PER_WARP], v1[ROWS_PER_WARP];
#pragma unroll
    for (int k = 0; k < ROWS_PER_WARP; k++) {
        const int row = gw + k * (NBLK * WARPS);
        const float4* p = reinterpret_cast<const float4*>(pts) + (size_t)row * (D / 4);
        v0[k] = p[lane];        // cols 4*lane   .. +3
        v1[k] = p[32 + lane];   // cols 128+4*lane .. +3
    }

    // Per-row sum of squares; 4 interleaved warp reductions.
    float ss[ROWS_PER_WARP];
#pragma unroll
    for (int k = 0; k < ROWS_PER_WARP; k++) {
        ss[k] = v0[k].x * v0[k].x + v0[k].y * v0[k].y + v0[k].z * v0[k].z + v0[k].w * v0[k].w
              + v1[k].x * v1[k].x + v1[k].y * v1[k].y + v1[k].z * v1[k].z + v1[k].w * v1[k].w;
    }
#pragma unroll
    for (int off = 16; off > 0; off >>= 1) {
#pragma unroll
        for (int k = 0; k < ROWS_PER_WARP; k++)
            ss[k] += __shfl_xor_sync(0xffffffffu, ss[k], off);
    }

    // rnorm * row into per-lane column accumulators.
    float4 a0 = make_float4(0.f, 0.f, 0.f, 0.f);
    float4 a1 = make_float4(0.f, 0.f, 0.f, 0.f);
#pragma unroll
    for (int k = 0; k < ROWS_PER_WARP; k++) {
        const float rn = rsqrtf(ss[k]);
        a0.x += rn * v0[k].x;  a0.y += rn * v0[k].y;
        a0.z += rn * v0[k].z;  a0.w += rn * v0[k].w;
        a1.x += rn * v1[k].x;  a1.y += rn * v1[k].y;
        a1.z += rn * v1[k].z;  a1.w += rn * v1[k].w;
    }

    // Block-reduce 8 warps' column partials via shared.
    __shared__ float sh[WARPS][D];
    float4* shv = reinterpret_cast<float4*>(sh[warp]);
    shv[lane]      = a0;
    shv[32 + lane] = a1;
    __syncthreads();

    float s = sh[0][t];
#pragma unroll
    for (int w = 1; w < WARPS; w++) s += sh[w][t];

    // Fire-and-forget RED into this block's replica; block retires immediately.
    atomicAdd(&g_rep[blockIdx.x & (NREP - 1)][t], s);
}

__global__ void __launch_bounds__(TPB)
k_fin(float* __restrict__ out) {
    const int t    = threadIdx.x;
    const int warp = t >> 5;
    const int lane = t & 31;

    // Fold the 16 replicas for this column (16 batched loads -> ~one memory trip),
    // and reset them for the next graph replay.
    float vr[NREP];
#pragma unroll
    for (int r = 0; r < NREP; r++) vr[r] = __ldcg(&g_rep[r][t]);
    float v = 0.0f;
#pragma unroll
    for (int r = 0; r < NREP; r++) { v += vr[r]; g_rep[r][t] = 0.0f; }

    double d = (double)v * (double)v;
#pragma unroll
    for (int off = 16; off > 0; off >>= 1)
        d += __shfl_xor_sync(0xffffffffu, d, off);

    __shared__ double wsum[WARPS];
    if (lane == 0) wsum[warp] = d;
    __syncthreads();
    if (warp == 0) {
        double x = (lane < WARPS) ? wsum[lane] : 0.0;
#pragma unroll
        for (int off = 4; off > 0; off >>= 1)
            x += __shfl_xor_sync(0xffffffffu, x, off);
        if (lane == 0) {
            const double n = (double)N_ROWS;
            out[0] = (float)((x - n) / (n * n));
        }
    }
}

extern "C" void kernel_launch(void* const* d_in, const int* in_sizes, int n_in,
                              void* d_out, int out_size) {
    const float* pts = (const float*)d_in[0];
    (void)in_sizes; (void)n_in; (void)out_size;
    k_stream<<<NBLK, TPB>>>(pts);
    k_fin<<<1, TPB>>>((float*)d_out);
}